// round 11
// baseline (speedup 1.0000x reference)
#include <cuda_runtime.h>
#include <cuda_fp16.h>
#include <math.h>
#include <stdint.h>

#define BB 2
#define SS 2048
#define EE 1024
#define HH 32
#define KK 8
#define DD 128
#define BSZ (BB*SS)     // 4096 tokens
#define BKH (BB*KK)     // 16 head-slots

// ---------------- scratch ----------------
static __device__ float  g_hw[BSZ*KK];
static __device__ float  g_probs[BSZ*HH];
static __device__ float  g_ent[BSZ];
static __device__ int    g_primary[BSZ];
static __device__ int    g_bcnt[HH];
static __device__ int    g_bucket[HH*BSZ];
static __device__ __half g_xh[(size_t)BSZ*EE];          // x in fp16
static __device__ __half g_wqt[(size_t)HH*DD*EE];       // Wq^T fp16 [n][k]
static __device__ __half g_wkt[(size_t)HH*DD*EE];
static __device__ __half g_wvt[(size_t)HH*DD*EE];
static __device__ __half g_wot[(size_t)EE*KK*DD];       // Wo^T fp16 [n=E][k=K*D]
static __device__ float  g_qf[(size_t)BKH*SS*DD];       // q fp32 (pre-rope)
static __device__ float  g_kf[(size_t)BKH*SS*DD];
static __device__ __half g_qh[(size_t)BKH*SS*DD];       // post-rope fp16, scaled by (1/sqrt(D))*log2e
static __device__ __half g_kh[(size_t)BKH*SS*DD];
static __device__ __half g_vh[(size_t)BKH*SS*DD];
static __device__ __half g_oh[(size_t)BSZ*KK*DD];       // attn output fp16

// ---------------- helpers ----------------
__device__ __forceinline__ float fexp2(float x) {
    float y;
    asm("ex2.approx.f32 %0, %1;" : "=f"(y) : "f"(x));
    return y;
}
__device__ __forceinline__ void mma16(float* cc, const uint32_t* a, uint32_t b0, uint32_t b1) {
    asm volatile(
        "mma.sync.aligned.m16n8k16.row.col.f32.f16.f16.f32 "
        "{%0,%1,%2,%3},{%4,%5,%6,%7},{%8,%9},{%0,%1,%2,%3};\n"
        : "+f"(cc[0]), "+f"(cc[1]), "+f"(cc[2]), "+f"(cc[3])
        : "r"(a[0]), "r"(a[1]), "r"(a[2]), "r"(a[3]), "r"(b0), "r"(b1));
}
__device__ __forceinline__ void ldsm4t(uint32_t& r0, uint32_t& r1, uint32_t& r2, uint32_t& r3,
                                       uint32_t addr) {
    asm volatile("ldmatrix.sync.aligned.m8n8.x4.trans.shared.b16 {%0,%1,%2,%3}, [%4];"
                 : "=r"(r0), "=r"(r1), "=r"(r2), "=r"(r3) : "r"(addr));
}
__device__ __forceinline__ uint32_t pack2(float a, float b) {
    __half2 h = __floats2half2_rn(a, b);
    return *(uint32_t*)&h;
}
__device__ __forceinline__ void cp16(void* smem, const void* gmem) {
    uint32_t a = (uint32_t)__cvta_generic_to_shared(smem);
    asm volatile("cp.async.cg.shared.global [%0], [%1], 16;\n" :: "r"(a), "l"(gmem));
}
__device__ __forceinline__ void cp_commit() { asm volatile("cp.async.commit_group;\n"); }
template<int N> __device__ __forceinline__ void cp_wait() {
    asm volatile("cp.async.wait_group %0;\n" :: "n"(N));
}

// ---------------- kernel 0 ----------------
__global__ void zero_kernel() {
    if (threadIdx.x < HH) g_bcnt[threadIdx.x] = 0;
}

// ---------------- prep: x -> fp16 ----------------
__global__ __launch_bounds__(256) void convx_kernel(const float* __restrict__ x) {
    int i = (blockIdx.x * 256 + threadIdx.x) * 4;
    float4 v = *(const float4*)(x + i);
    __half2* d = (__half2*)(g_xh + i);
    d[0] = __floats2half2_rn(v.x, v.y);
    d[1] = __floats2half2_rn(v.z, v.w);
}

// ---------------- prep: W transpose -> fp16 [n][k] ----------------
__global__ __launch_bounds__(256) void transpose_kernel(const float* __restrict__ Wq,
                                                        const float* __restrict__ Wk,
                                                        const float* __restrict__ Wv,
                                                        const float* __restrict__ Wo) {
    const int z = blockIdx.z;
    const float* src = (z == 0) ? Wq : (z == 1) ? Wk : (z == 2) ? Wv : Wo;
    __half* dst = (z == 0) ? g_wqt : (z == 1) ? g_wkt : (z == 2) ? g_wvt : g_wot;
    const int C = (z < 3) ? (HH * DD) : EE;
    const int R = EE;
    const int c0 = blockIdx.x * 32, r0 = blockIdx.y * 32;
    if (c0 >= C) return;
    __shared__ float t[32][33];
    const int tx = threadIdx.x & 31, ty = threadIdx.x >> 5;
    #pragma unroll
    for (int i = 0; i < 4; i++)
        t[ty + 8 * i][tx] = src[(size_t)(r0 + ty + 8 * i) * C + c0 + tx];
    __syncthreads();
    #pragma unroll
    for (int i = 0; i < 4; i++)
        dst[(size_t)(c0 + ty + 8 * i) * R + r0 + tx] = __float2half(t[tx][ty + 8 * i]);
}

// ---------------- kernel 1: router (exact fp32) ----------------
__global__ __launch_bounds__(256) void router_kernel(const float* __restrict__ x,
                                                     const float* __restrict__ Wr) {
    const int token = blockIdx.x;
    __shared__ float xs[EE];
    __shared__ float part[8][HH];
    __shared__ float s_topv[KK];
    __shared__ int   s_topi[KK];
    const int tid = threadIdx.x;

    const float4* xv = (const float4*)(x + (size_t)token * EE);
    float4* xsv = (float4*)xs;
    for (int i = tid; i < EE/4; i += 256) xsv[i] = xv[i];
    __syncthreads();

    const int warp = tid >> 5, lane = tid & 31;
    float acc = 0.f;
    const int e0 = warp * 128;
    #pragma unroll 4
    for (int e = 0; e < 128; e++)
        acc = fmaf(xs[e0 + e], Wr[(size_t)(e0 + e) * HH + lane], acc);
    part[warp][lane] = acc;
    __syncthreads();

    if (warp == 0) {
        float logit = 0.f;
        #pragma unroll
        for (int w = 0; w < 8; w++) logit += part[w][lane];

        float m = logit;
        #pragma unroll
        for (int o = 16; o; o >>= 1) m = fmaxf(m, __shfl_xor_sync(0xffffffffu, m, o));
        float ex = expf(logit - m);
        float sum = ex;
        #pragma unroll
        for (int o = 16; o; o >>= 1) sum += __shfl_xor_sync(0xffffffffu, sum, o);
        float prob = ex / sum;
        g_probs[(size_t)token * HH + lane] = prob;
        float et = -prob * logf(prob + 1e-8f);
        #pragma unroll
        for (int o = 16; o; o >>= 1) et += __shfl_xor_sync(0xffffffffu, et, o);
        if (lane == 0) g_ent[token] = et;

        float cur = logit;
        for (int j = 0; j < KK; j++) {
            float bv = cur; int bi = lane;
            #pragma unroll
            for (int o = 16; o; o >>= 1) {
                float ov = __shfl_xor_sync(0xffffffffu, bv, o);
                int   oi = __shfl_xor_sync(0xffffffffu, bi, o);
                if (ov > bv || (ov == bv && oi < bi)) { bv = ov; bi = oi; }
            }
            if (lane == 0) { s_topv[j] = bv; s_topi[j] = bi; }
            if (lane == bi) cur = -INFINITY;
        }
        __syncwarp();

        if (lane < KK) {
            float tv = s_topv[lane];
            float e2 = expf(tv - s_topv[0]);
            float s2 = e2;
            #pragma unroll
            for (int o = 4; o; o >>= 1) s2 += __shfl_xor_sync(0x000000ffu, s2, o, 8);
            int hsel = s_topi[lane];
            g_hw[token * KK + lane] = e2 / s2;
            int pos = atomicAdd(&g_bcnt[hsel], 1);
            g_bucket[hsel * BSZ + pos] = token * KK + lane;
        }
        if (lane == 0) g_primary[token] = s_topi[0];
    }
}

// ---------------- kernel 2: bucketed gather projection, fp16 MMA + cp.async ----------------
#define XBUF (128 * 72)                 // halves per buffer
#define PROJ_SMEM (6 * XBUF * 2)        // X0..2 + W0..2
__global__ __launch_bounds__(256) void proj_mma_kernel() {
    const int h = blockIdx.y;
    const int cnt = g_bcnt[h];
    const int t0 = blockIdx.x * 128;
    if (t0 >= cnt) return;
    const int mat = blockIdx.z;
    const __half* Wt = (mat == 0 ? g_wqt : mat == 1 ? g_wkt : g_wvt);

    extern __shared__ __half psm[];
    __half* Xbase = psm;
    __half* Wbase = psm + 3 * XBUF;
    __shared__ int codes[128];

    const int tid = threadIdx.x;
    const int lane = tid & 31, warp = tid >> 5;
    const int g = lane >> 2, c = lane & 3;
    const int wr = (warp >> 1) * 32;
    const int wc = (warp & 1) * 64;

    if (tid < 128) {
        int ii = t0 + tid;
        codes[tid] = (ii < cnt) ? g_bucket[h * BSZ + ii] : -1;
    }
    __syncthreads();

    const int srow = tid >> 1;
    const int soff = (tid & 1) * 32;
    int mycode = codes[srow];
    const __half* xrow = g_xh + (size_t)(mycode >= 0 ? (mycode >> 3) : 0) * EE + soff;
    const __half* wrow = Wt + (size_t)(h * DD + srow) * EE + soff;

    float acc[2][8][4];
    #pragma unroll
    for (int mt = 0; mt < 2; mt++)
        #pragma unroll
        for (int nt = 0; nt < 8; nt++)
            #pragma unroll
            for (int q = 0; q < 4; q++) acc[mt][nt][q] = 0.f;

    #pragma unroll
    for (int p = 0; p < 2; p++) {
        __half* xd = Xbase + p * XBUF + srow * 72 + soff;
        __half* wd = Wbase + p * XBUF + srow * 72 + soff;
        #pragma unroll
        for (int j = 0; j < 4; j++) {
            cp16(xd + 8 * j, xrow + p * 64 + 8 * j);
            cp16(wd + 8 * j, wrow + p * 64 + 8 * j);
        }
        cp_commit();
    }

    for (int cch = 0; cch < 16; cch++) {
        if (cch < 14) cp_wait<1>(); else cp_wait<0>();
        __syncthreads();
        if (cch + 2 < 16) {
            int b = (cch + 2) % 3;
            __half* xd = Xbase + b * XBUF + srow * 72 + soff;
            __half* wd = Wbase + b * XBUF + srow * 72 + soff;
            #pragma unroll
            for (int j = 0; j < 4; j++) {
                cp16(xd + 8 * j, xrow + (cch + 2) * 64 + 8 * j);
                cp16(wd + 8 * j, wrow + (cch + 2) * 64 + 8 * j);
            }
            cp_commit();
        }
        const __half* Xs = Xbase + (cch % 3) * XBUF;
        const __half* Ws = Wbase + (cch % 3) * XBUF;
        #pragma unroll
        for (int ks = 0; ks < 4; ks++) {
            uint32_t a[2][4];
            #pragma unroll
            for (int mt = 0; mt < 2; mt++) {
                int row = wr + mt * 16;
                a[mt][0] = *(const uint32_t*)(Xs + (row + g    ) * 72 + 16*ks + 2*c);
                a[mt][1] = *(const uint32_t*)(Xs + (row + g + 8) * 72 + 16*ks + 2*c);
                a[mt][2] = *(const uint32_t*)(Xs + (row + g    ) * 72 + 16*ks + 2*c + 8);
                a[mt][3] = *(const uint32_t*)(Xs + (row + g + 8) * 72 + 16*ks + 2*c + 8);
            }
            #pragma unroll
            for (int nt = 0; nt < 8; nt++) {
                int n = wc + nt * 8 + g;
                uint32_t b0 = *(const uint32_t*)(Ws + n * 72 + 16*ks + 2*c);
                uint32_t b1 = *(const uint32_t*)(Ws + n * 72 + 16*ks + 2*c + 8);
                mma16(acc[0][nt], a[0], b0, b1);
                mma16(acc[1][nt], a[1], b0, b1);
            }
        }
        __syncthreads();
    }

    #pragma unroll
    for (int mt = 0; mt < 2; mt++) {
        int r0 = wr + mt * 16 + g;
        int r1 = r0 + 8;
        int code0 = codes[r0], code1 = codes[r1];
        size_t base0 = 0, base1 = 0;
        if (code0 >= 0) {
            int token = code0 >> 3, slot = code0 & 7;
            base0 = ((size_t)(((token >> 11) * KK + slot) * SS + (token & (SS-1)))) * DD;
        }
        if (code1 >= 0) {
            int token = code1 >> 3, slot = code1 & 7;
            base1 = ((size_t)(((token >> 11) * KK + slot) * SS + (token & (SS-1)))) * DD;
        }
        #pragma unroll
        for (int nt = 0; nt < 8; nt++) {
            int col = wc + nt * 8 + 2 * c;
            if (mat == 2) {
                if (code0 >= 0)
                    *(__half2*)&g_vh[base0 + col] = __floats2half2_rn(acc[mt][nt][0], acc[mt][nt][1]);
                if (code1 >= 0)
                    *(__half2*)&g_vh[base1 + col] = __floats2half2_rn(acc[mt][nt][2], acc[mt][nt][3]);
            } else {
                float* dst = (mat == 0) ? g_qf : g_kf;
                if (code0 >= 0) { float2 v = { acc[mt][nt][0], acc[mt][nt][1] }; *(float2*)&dst[base0 + col] = v; }
                if (code1 >= 0) { float2 v = { acc[mt][nt][2], acc[mt][nt][3] }; *(float2*)&dst[base1 + col] = v; }
            }
        }
    }
}

// ---------------- kernel 3: RoPE fp32 -> fp16; q gets (1/sqrt(D))*log2e ----------------
__global__ __launch_bounds__(256) void rope_kernel() {
    int idx = blockIdx.x * blockDim.x + threadIdx.x;
    const int total = BKH * SS * 32;
    if (idx >= total) return;
    int d2 = idx & 31;
    int rest = idx >> 5;
    int s = rest & (SS - 1);
    int d0 = 2 * d2;
    const float Cf = 9.210340371976184f / 64.f;
    float inv0 = expf(-(float)d0 * Cf);
    float inv1 = expf(-(float)(d0 + 1) * Cf);
    float sn0, cs0, sn1, cs1;
    sincosf(s * inv0, &sn0, &cs0);
    sincosf(s * inv1, &sn1, &cs1);
    const float scale = 0.12751691579231338f;  // (1/sqrt(128)) * log2(e)
    size_t i0 = ((size_t)rest << 7) + d0;
    float qa = g_qf[i0], qb = g_qf[i0+1], qc_ = g_qf[i0+64], qd = g_qf[i0+65];
    *(__half2*)&g_qh[i0]      = __floats2half2_rn((qa*cs0 - qc_*sn0)*scale, (qb*cs1 - qd*sn1)*scale);
    *(__half2*)&g_qh[i0 + 64] = __floats2half2_rn((qc_*cs0 + qa*sn0)*scale, (qd*cs1 + qb*sn1)*scale);
    float ka = g_kf[i0], kb_ = g_kf[i0+1], kc_ = g_kf[i0+64], kd = g_kf[i0+65];
    *(__half2*)&g_kh[i0]      = __floats2half2_rn(ka*cs0 - kc_*sn0, kb_*cs1 - kd*sn1);
    *(__half2*)&g_kh[i0 + 64] = __floats2half2_rn(kc_*cs0 + ka*sn0, kd*cs1 + kb_*sn1);
}

// ---------------- kernel 4: flash attention fp16, paired q-tiles, single wave ----------------
// grid (BKH, 8): block handles q-tiles {15 - y, y} -> constant work 34 units/block.
__global__ __launch_bounds__(256, 1) void attn_mma_kernel() {
    __shared__ __half Ks[64][136];
    __shared__ __half Vs[64][136];

    const int bk = blockIdx.x;
    const int b = bk >> 3, kslot = bk & 7;
    const int tid = threadIdx.x;
    const int lane = tid & 31, warp = tid >> 5;
    const int g = lane >> 2, c = lane & 3;

    const __half* Qp = g_qh + (size_t)bk * SS * DD;
    const __half* Kp = g_kh + (size_t)bk * SS * DD;
    const __half* Vp = g_vh + (size_t)bk * SS * DD;

    const int lrow = tid >> 2;
    const int coff = (tid & 3) * 32;
    const uint32_t vs_base = (uint32_t)__cvta_generic_to_shared(&Vs[0][0]);

    for (int half = 0; half < 2; half++) {
        const int qt = (half == 0) ? (15 - (int)blockIdx.y) : (int)blockIdx.y;
        const int qbase = qt * 128;

        // stage K0
        {
            const __half* src = Kp + (size_t)lrow * DD + coff;
            #pragma unroll
            for (int j = 0; j < 4; j++) cp16(&Ks[lrow][coff + 8*j], src + 8*j);
            cp_commit();
        }

        const int r0 = qbase + warp * 16 + g;
        const int r1 = r0 + 8;
        uint32_t qf[8][4];
        {
            const __half* q0 = Qp + (size_t)r0 * DD;
            const __half* q1 = Qp + (size_t)r1 * DD;
            #pragma unroll
            for (int ks = 0; ks < 8; ks++) {
                qf[ks][0] = *(const uint32_t*)(q0 + 16*ks + 2*c);
                qf[ks][1] = *(const uint32_t*)(q1 + 16*ks + 2*c);
                qf[ks][2] = *(const uint32_t*)(q0 + 16*ks + 2*c + 8);
                qf[ks][3] = *(const uint32_t*)(q1 + 16*ks + 2*c + 8);
            }
        }

        float o[16][4];
        #pragma unroll
        for (int nt = 0; nt < 16; nt++)
            #pragma unroll
            for (int q = 0; q < 4; q++) o[nt][q] = 0.f;
        float m0 = -INFINITY, m1 = -INFINITY, l0 = 0.f, l1 = 0.f;

        const int nkt = 2 * qt + 2;
        const int wlast = qbase + warp * 16 + 16;

        float s[8][4];
        uint32_t pa[4][4];

        for (int kt = 0; kt < nkt; kt++) {
            const int kb = kt * 64;
            const bool act = (kb < wlast);
            cp_wait<0>();
            __syncthreads();

            {
                const __half* src = Vp + (size_t)(kb + lrow) * DD + coff;
                #pragma unroll
                for (int j = 0; j < 4; j++) cp16(&Vs[lrow][coff + 8*j], src + 8*j);
                cp_commit();
            }

            if (act) {
                #pragma unroll
                for (int nt = 0; nt < 8; nt++)
                    #pragma unroll
                    for (int q = 0; q < 4; q++) s[nt][q] = 0.f;
                #pragma unroll
                for (int ks = 0; ks < 8; ks++) {
                    #pragma unroll
                    for (int nt = 0; nt < 8; nt++) {
                        int n = nt * 8 + g;
                        uint32_t b0 = *(const uint32_t*)(&Ks[n][16*ks + 2*c]);
                        uint32_t b1 = *(const uint32_t*)(&Ks[n][16*ks + 2*c + 8]);
                        mma16(s[nt], qf[ks], b0, b1);
                    }
                }
            }
            __syncthreads();

            if (kt + 1 < nkt) {
                const __half* src = Kp + (size_t)(kb + 64 + lrow) * DD + coff;
                #pragma unroll
                for (int j = 0; j < 4; j++) cp16(&Ks[lrow][coff + 8*j], src + 8*j);
                cp_commit();
            }

            if (act) {
                if (kb + 63 > r0) {
                    #pragma unroll
                    for (int nt = 0; nt < 8; nt++) {
                        int col = kb + nt * 8 + 2 * c;
                        if (col     > r0) s[nt][0] = -INFINITY;
                        if (col + 1 > r0) s[nt][1] = -INFINITY;
                        if (col     > r1) s[nt][2] = -INFINITY;
                        if (col + 1 > r1) s[nt][3] = -INFINITY;
                    }
                }
                float mx0 = -INFINITY, mx1 = -INFINITY;
                #pragma unroll
                for (int nt = 0; nt < 8; nt++) {
                    mx0 = fmaxf(mx0, fmaxf(s[nt][0], s[nt][1]));
                    mx1 = fmaxf(mx1, fmaxf(s[nt][2], s[nt][3]));
                }
                #pragma unroll
                for (int off = 1; off <= 2; off <<= 1) {
                    mx0 = fmaxf(mx0, __shfl_xor_sync(0xffffffffu, mx0, off));
                    mx1 = fmaxf(mx1, __shfl_xor_sync(0xffffffffu, mx1, off));
                }
                float mn0 = fmaxf(m0, mx0), mn1 = fmaxf(m1, mx1);
                float al0 = fexp2(m0 - mn0), al1 = fexp2(m1 - mn1);
                m0 = mn0; m1 = mn1;
                float rs0 = 0.f, rs1 = 0.f;
                #pragma unroll
                for (int nt = 0; nt < 8; nt++) {
                    s[nt][0] = fexp2(s[nt][0] - mn0);
                    s[nt][1] = fexp2(s[nt][1] - mn0);
                    s[nt][2] = fexp2(s[nt][2] - mn1);
                    s[nt][3] = fexp2(s[nt][3] - mn1);
                    rs0 += s[nt][0] + s[nt][1];
                    rs1 += s[nt][2] + s[nt][3];
                }
                #pragma unroll
                for (int off = 1; off <= 2; off <<= 1) {
                    rs0 += __shfl_xor_sync(0xffffffffu, rs0, off);
                    rs1 += __shfl_xor_sync(0xffffffffu, rs1, off);
                }
                l0 = l0 * al0 + rs0;
                l1 = l1 * al1 + rs1;
                #pragma unroll
                for (int nt = 0; nt < 16; nt++) {
                    o[nt][0] *= al0; o[nt][1] *= al0;
                    o[nt][2] *= al1; o[nt][3] *= al1;
                }
                #pragma unroll
                for (int k2 = 0; k2 < 4; k2++) {
                    pa[k2][0] = pack2(s[2*k2][0],   s[2*k2][1]);
                    pa[k2][1] = pack2(s[2*k2][2],   s[2*k2][3]);
                    pa[k2][2] = pack2(s[2*k2+1][0], s[2*k2+1][1]);
                    pa[k2][3] = pack2(s[2*k2+1][2], s[2*k2+1][3]);
                }
            }

            if (kt + 1 < nkt) cp_wait<1>(); else cp_wait<0>();
            __syncthreads();

            if (act) {
                #pragma unroll
                for (int k2 = 0; k2 < 4; k2++) {
                    int kv0 = k2 * 16;
                    #pragma unroll
                    for (int ntp = 0; ntp < 8; ntp++) {
                        int row = kv0 + (lane & 15);
                        int col = ntp * 16 + (lane >> 4) * 8;
                        uint32_t addr = vs_base + (uint32_t)(row * 136 + col) * 2;
                        uint32_t r0v, r1v, r2v, r3v;
                        ldsm4t(r0v, r1v, r2v, r3v, addr);
                        mma16(o[2*ntp],     pa[k2], r0v, r1v);
                        mma16(o[2*ntp + 1], pa[k2], r2v, r3v);
                    }
                }
            }
        }

        // epilogue for this q-tile
        int token0 = b * SS + r0;
        int token1 = b * SS + r1;
        float w0 = g_hw[token0 * KK + kslot] / l0;
        float w1 = g_hw[token1 * KK + kslot] / l1;
        size_t base0 = ((size_t)token0 * KK + kslot) * DD;
        size_t base1 = ((size_t)token1 * KK + kslot) * DD;
        #pragma unroll
        for (int nt = 0; nt < 16; nt++) {
            int col = nt * 8 + 2 * c;
            *(__half2*)&g_oh[base0 + col] = __floats2half2_rn(o[nt][0] * w0, o[nt][1] * w0);
            *(__half2*)&g_oh[base1 + col] = __floats2half2_rn(o[nt][2] * w1, o[nt][3] * w1);
        }
    }
}

// ---------------- kernel 5: output projection fp16 ----------------
#define OUT_SMEM (6 * XBUF * 2)
__global__ __launch_bounds__(256) void outproj_mma_kernel(float* __restrict__ out) {
    const int rbase = blockIdx.x * 128;
    const int cbase = blockIdx.y * 128;

    extern __shared__ __half osm[];
    __half* Xbase = osm;
    __half* Wbase = osm + 3 * XBUF;

    const int tid = threadIdx.x;
    const int lane = tid & 31, warp = tid >> 5;
    const int g = lane >> 2, c = lane & 3;
    const int wr = (warp >> 1) * 32;
    const int wc = (warp & 1) * 64;

    const int srow = tid >> 1;
    const int soff = (tid & 1) * 32;
    const __half* arow = g_oh + (size_t)(rbase + srow) * EE + soff;
    const __half* wrow = g_wot + (size_t)(cbase + srow) * (KK * DD) + soff;

    float acc[2][8][4];
    #pragma unroll
    for (int mt = 0; mt < 2; mt++)
        #pragma unroll
        for (int nt = 0; nt < 8; nt++)
            #pragma unroll
            for (int q = 0; q < 4; q++) acc[mt][nt][q] = 0.f;

    #pragma unroll
    for (int p = 0; p < 2; p++) {
        __half* xd = Xbase + p * XBUF + srow * 72 + soff;
        __half* wd = Wbase + p * XBUF + srow * 72 + soff;
        #pragma unroll
        for (int j = 0; j < 4; j++) {
            cp16(xd + 8 * j, arow + p * 64 + 8 * j);
            cp16(wd + 8 * j, wrow + p * 64 + 8 * j);
        }
        cp_commit();
    }

    for (int cch = 0; cch < 16; cch++) {
        if (cch < 14) cp_wait<1>(); else cp_wait<0>();
        __syncthreads();
        if (cch + 2 < 16) {
            int bq = (cch + 2) % 3;
            __half* xd = Xbase + bq * XBUF + srow * 72 + soff;
            __half* wd = Wbase + bq * XBUF + srow * 72 + soff;
            #pragma unroll
            for (int j = 0; j < 4; j++) {
                cp16(xd + 8 * j, arow + (cch + 2) * 64 + 8 * j);
                cp16(wd + 8 * j, wrow + (cch + 2) * 64 + 8 * j);
            }
            cp_commit();
        }
        const __half* Xs = Xbase + (cch % 3) * XBUF;
        const __half* Ws = Wbase + (cch % 3) * XBUF;
        #pragma unroll
        for (int ks = 0; ks < 4; ks++) {
            uint32_t a[2][4];
            #pragma unroll
            for (int mt = 0; mt < 2; mt++) {
                int row = wr + mt * 16;
                a[mt][0] = *(const uint32_t*)(Xs + (row + g    ) * 72 + 16*ks + 2*c);
                a[mt][1] = *(const uint32_t*)(Xs + (row + g + 8) * 72 + 16*ks + 2*c);
                a[mt][2] = *(const uint32_t*)(Xs + (row + g    ) * 72 + 16*ks + 2*c + 8);
                a[mt][3] = *(const uint32_t*)(Xs + (row + g + 8) * 72 + 16*ks + 2*c + 8);
            }
            #pragma unroll
            for (int nt = 0; nt < 8; nt++) {
                int n = wc + nt * 8 + g;
                uint32_t b0 = *(const uint32_t*)(Ws + n * 72 + 16*ks + 2*c);
                uint32_t b1 = *(const uint32_t*)(Ws + n * 72 + 16*ks + 2*c + 8);
                mma16(acc[0][nt], a[0], b0, b1);
                mma16(acc[1][nt], a[1], b0, b1);
            }
        }
        __syncthreads();
    }

    #pragma unroll
    for (int mt = 0; mt < 2; mt++) {
        size_t row0 = rbase + wr + mt * 16 + g;
        size_t row1 = row0 + 8;
        #pragma unroll
        for (int nt = 0; nt < 8; nt++) {
            int col = cbase + wc + nt * 8 + 2 * c;
            float2 v0 = { acc[mt][nt][0], acc[mt][nt][1] };
            float2 v1 = { acc[mt][nt][2], acc[mt][nt][3] };
            *(float2*)&out[row0 * EE + col] = v0;
            *(float2*)&out[row1 * EE + col] = v1;
        }
    }
}

// ---------------- kernel 6: finalize (parallel) ----------------
__global__ __launch_bounds__(512) void finalize_kernel(float* __restrict__ out, int out_size) {
    __shared__ float s_bal[BB * HH];
    __shared__ float s_ent[512];
    const int tid = threadIdx.x;
    {
        int pair = tid >> 3, sub = tid & 7;
        int b = pair >> 5, h = pair & 31;
        float psum = 0.f, fcnt = 0.f;
        for (int s = sub; s < SS; s += 8) {
            int t = b * SS + s;
            psum += g_probs[(size_t)t * HH + h];
            fcnt += (g_primary[t] == h) ? 1.f : 0.f;
        }
        #pragma unroll
        for (int off = 4; off; off >>= 1) {
            psum += __shfl_xor_sync(0xffffffffu, psum, off);
            fcnt += __shfl_xor_sync(0xffffffffu, fcnt, off);
        }
        if (sub == 0) s_bal[pair] = (fcnt / SS) * (psum / SS);
    }
    {
        float e = 0.f;
        for (int i = tid; i < BSZ; i += 512) e += g_ent[i];
        s_ent[tid] = e;
    }
    __syncthreads();
    for (int h = 256; h >= 1; h >>= 1) {
        if (tid < h) s_ent[tid] += s_ent[tid + h];
        __syncthreads();
    }
    const int base = BSZ * EE;
    if (tid == 0 && out_size > base) {
        float bal = 0.f;
        for (int i = 0; i < BB * HH; i++) bal += s_bal[i];
        bal = (float)HH * (bal / BB);
        float ent = s_ent[0] / (float)BSZ;
        out[out_size - 1] = bal - 0.01f * ent;
    }
    if (out_size > base) {
        for (int i = base + tid; i < out_size - 1; i += 512) out[i] = 0.f;
    }
}

// ---------------- launcher ----------------
extern "C" void kernel_launch(void* const* d_in, const int* in_sizes, int n_in,
                              void* d_out, int out_size) {
    const float* x  = (const float*)d_in[0];
    const float* Wq = (const float*)d_in[1];
    const float* Wk = (const float*)d_in[2];
    const float* Wv = (const float*)d_in[3];
    const float* Wr = (const float*)d_in[4];
    const float* Wo = (const float*)d_in[5];
    for (int i = 0; i < n_in; i++) {
        if (in_sizes[i] == EE * HH)      Wr = (const float*)d_in[i];
        if (in_sizes[i] == KK * DD * EE) Wo = (const float*)d_in[i];
    }
    float* out = (float*)d_out;

    static int attr_set = 0;
    if (!attr_set) {
        cudaFuncSetAttribute(proj_mma_kernel,
                             cudaFuncAttributeMaxDynamicSharedMemorySize, PROJ_SMEM);
        cudaFuncSetAttribute(outproj_mma_kernel,
                             cudaFuncAttributeMaxDynamicSharedMemorySize, OUT_SMEM);
        attr_set = 1;
    }

    zero_kernel<<<1, 32>>>();
    convx_kernel<<<BSZ * EE / 1024, 256>>>(x);
    transpose_kernel<<<dim3((HH * DD) / 32, EE / 32, 4), 256>>>(Wq, Wk, Wv, Wo);
    router_kernel<<<BSZ, 256>>>(x, Wr);
    proj_mma_kernel<<<dim3(32, HH, 3), 256, PROJ_SMEM>>>();
    rope_kernel<<<BKH * SS * 32 / 256, 256>>>();
    attn_mma_kernel<<<dim3(BKH, 8), 256>>>();
    outproj_mma_kernel<<<dim3(BSZ / 128, EE / 128), 256, OUT_SMEM>>>(out);
    finalize_kernel<<<1, 512>>>(out, out_size);
}